// round 2
// baseline (speedup 1.0000x reference)
#include <cuda_runtime.h>
#include <math.h>

#define FULLMASK 0xffffffffu
constexpr int B_ = 32, N_ = 16384, M_ = 128, PW = 86, NLOG = 80;
constexpr int CHUNK = 512, BLKX = N_ / CHUNK, NWARP = 8;
constexpr float NEGV = -1000000000.0f;

// per-(image,block) partials:
// [0]=n_m [1]=s_bbox [2]=s_nll [3]=s_bce1 [4]=s_bce0_unmatched [5]=s_bce0_all
// [6]=fb_max [7]=fb_n [8]=fb_bbox [9]=fb_nll [10]=fb_bce1 [11]=fb_bce0
__device__ float g_part[B_ * BLKX * 12];

__device__ __forceinline__ float sl1(float x, float y) {
  float d = x - y, ad = fabsf(d);
  return ad < 1.0f ? 0.5f * d * d : ad - 0.5f;
}
__device__ __forceinline__ int f2ord(float f) {
  int i = __float_as_int(f);
  return i ^ ((i >> 31) & 0x7fffffff);
}
__device__ __forceinline__ float ord2f(int k) {
  return __int_as_float(k ^ ((k >> 31) & 0x7fffffff));
}

__global__ __launch_bounds__(256) void det_loss_main(
    const float* __restrict__ preds, const float* __restrict__ targets) {
  const int b = blockIdx.y;
  const int tid = threadIdx.x, wid = tid >> 5, lane = tid & 31;

  __shared__ float tx1[M_], ty1[M_], tx2[M_], ty2[M_], tcl[M_];
  __shared__ float cx1[M_], cy1[M_], cx2[M_], cy2[M_], ca2[M_];
  __shared__ int cixs[M_];
  __shared__ int sV;
  __shared__ float wacc[NWARP][12];

  if (tid < M_) {
    const float* t = targets + ((size_t)b * M_ + tid) * 5;
    tx1[tid] = t[0]; ty1[tid] = t[1]; tx2[tid] = t[2]; ty2[tid] = t[3]; tcl[tid] = t[4];
  }
  __syncthreads();

  // warp 0: order-preserving ballot compaction of valid targets
  if (wid == 0) {
    int base = 0;
#pragma unroll
    for (int g = 0; g < 4; g++) {
      int m = g * 32 + lane;
      bool val = tcl[m] != -1.0f;
      unsigned bal = __ballot_sync(FULLMASK, val);
      int pos = base + __popc(bal & ((1u << lane) - 1u));
      if (val) {
        cx1[pos] = tx1[m]; cy1[pos] = ty1[m]; cx2[pos] = tx2[m]; cy2[pos] = ty2[m];
        ca2[pos] = (tx2[m] - tx1[m]) * (ty2[m] - ty1[m]);
        cixs[pos] = m;
      }
      base += __popc(bal);
    }
    if (lane == 0) sV = base;
  }
  __syncthreads();
  const int V = sV;
  const int nc = (V + 31) >> 5;

  float kx1[4], ky1[4], kx2[4], ky2[4], ka2[4];
  int kix[4]; bool kok[4];
#pragma unroll
  for (int c = 0; c < 4; c++) {
    int m = lane + 32 * c;
    bool ok = m < V;
    int mm = ok ? m : 0;
    kx1[c] = cx1[mm]; ky1[c] = cy1[mm]; kx2[c] = cx2[mm]; ky2[c] = cy2[mm];
    ka2[c] = ca2[mm]; kix[c] = cixs[mm]; kok[c] = ok;
  }
  const int cix0 = (V > 0) ? cixs[0] : 0;

  float n_m = 0.f, s_bb = 0.f, s_nll = 0.f, s_b1 = 0.f, s_b0u = 0.f, s_all = 0.f;
  float fmx = -INFINITY, fn = 0.f, fbb = 0.f, fnll = 0.f, fb1 = 0.f, fb0 = 0.f;

  const int n0 = blockIdx.x * CHUNK;
  for (int n = n0 + wid; n < n0 + CHUNK; n += NWARP) {
    const float* row = preds + ((size_t)b * N_ + n) * PW;
    float r0 = __ldg(row + lane);
    float pb0 = __shfl_sync(FULLMASK, r0, 0);
    float pb1 = __shfl_sync(FULLMASK, r0, 1);
    float pb2 = __shfl_sync(FULLMASK, r0, 2);
    float pb3 = __shfl_sync(FULLMASK, r0, 3);
    float conf = __shfl_sync(FULLMASK, r0, 4);
    float bce0 = -fmaxf(log1pf(-conf), -100.0f);
    s_all += bce0;

    float pdx = pb2 - pb0, pdy = pb3 - pb1;
    float a1 = pdx * pdy;

    float biou; int bidx;
    if (pdx > 0.0f && pdy > 0.0f) {
      biou = NEGV; bidx = cix0;
#pragma unroll
      for (int c = 0; c < 4; c++) {
        if (c >= nc) break;
        float x1 = fmaxf(pb0, kx1[c]);
        float y1 = fmaxf(pb1, ky1[c]);
        float x2 = fminf(pb2, kx2[c]);
        float y2 = fminf(pb3, ky2[c]);
        float inter = fmaxf(x2 - x1, 0.0f) * fmaxf(y2 - y1, 0.0f);
        float den = (a1 + ka2[c]) - inter + 1e-6f;
        float iou = __fdividef(inter, den);
        if (iou == 0.0f) iou = 0.0f;  // canonicalize -0 -> +0 (JAX tie semantics)
        if (kok[c] && iou > biou) { biou = iou; bidx = kix[c]; }
      }
      int kmax = __reduce_max_sync(FULLMASK, f2ord(biou));
      float wiou = ord2f(kmax);
      unsigned candx = (biou == wiou) ? (unsigned)bidx : 0xffffffffu;
      unsigned widx = __reduce_min_sync(FULLMASK, candx);
      biou = wiou;
      bidx = (widx < (unsigned)M_) ? (int)widx : cix0;
    } else {
      // degenerate pred box: inter==0 vs every target
      biou = (V > 0) ? 0.0f : NEGV;
      bidx = cix0;
    }

    bool matched = biou > 0.4f;
    if (!matched) s_b0u += bce0;

    if (matched || biou >= fmx) {
      float r1 = __ldg(row + 32 + lane);
      float r2 = (lane < 22) ? __ldg(row + 64 + lane) : 0.0f;
      float g0 = tx1[bidx], g1 = ty1[bidx], g2 = tx2[bidx], g3 = ty2[bidx];
      float ga = (g2 - g0) * (g3 - g1);
      float w = (ga < 0.01f) ? 1.5f : 1.0f;
      float bbox_t = (sl1(pb0, g0) + sl1(pb1, g1) + sl1(pb2, g2) + sl1(pb3, g3)) * w;

      float l0 = (lane >= 6) ? r0 : -1e30f;
      float l2 = (lane < 22) ? r2 : -1e30f;
      float mx = fmaxf(l0, fmaxf(r1, l2));
      mx = ord2f(__reduce_max_sync(FULLMASK, f2ord(mx)));
      float se = __expf(l0 - mx) + __expf(r1 - mx) + __expf(l2 - mx);
#pragma unroll
      for (int off = 16; off; off >>= 1) se += __shfl_xor_sync(FULLMASK, se, off);
      int e = min(max((int)tcl[bidx], 0), NLOG - 1) + 6;
      float lv;
      if (e < 32)      lv = __shfl_sync(FULLMASK, r0, e);
      else if (e < 64) lv = __shfl_sync(FULLMASK, r1, e - 32);
      else             lv = __shfl_sync(FULLMASK, r2, e - 64);
      float nll = (mx + __logf(se)) - lv;
      float bce1 = -fmaxf(__logf(conf), -100.0f);

      if (matched) { n_m += 1.0f; s_bb += bbox_t; s_nll += nll; s_b1 += bce1; }
      if (biou > fmx) { fmx = biou; fn = 1.0f; fbb = bbox_t; fnll = nll; fb1 = bce1; fb0 = bce0; }
      else if (biou == fmx) { fn += 1.0f; fbb += bbox_t; fnll += nll; fb1 += bce1; fb0 += bce0; }
    }
  }

  if (lane == 0) {
    float* a = wacc[wid];
    a[0] = n_m; a[1] = s_bb; a[2] = s_nll; a[3] = s_b1; a[4] = s_b0u; a[5] = s_all;
    a[6] = fmx; a[7] = fn; a[8] = fbb; a[9] = fnll; a[10] = fb1; a[11] = fb0;
  }
  __syncthreads();
  if (tid == 0) {
    float o[12];
#pragma unroll
    for (int k = 0; k < 12; k++) o[k] = wacc[0][k];
    for (int wv = 1; wv < NWARP; wv++) {
      float* a = wacc[wv];
#pragma unroll
      for (int k = 0; k < 6; k++) o[k] += a[k];
      if (a[6] > o[6]) {
#pragma unroll
        for (int k = 6; k < 12; k++) o[k] = a[k];
      } else if (a[6] == o[6]) {
#pragma unroll
        for (int k = 7; k < 12; k++) o[k] += a[k];
      }
    }
    float* g = g_part + ((size_t)b * BLKX + blockIdx.x) * 12;
#pragma unroll
    for (int k = 0; k < 12; k++) g[k] = o[k];
  }
}

__global__ void det_loss_final(const float* __restrict__ targets,
                               float* __restrict__ out) {
  __shared__ float sh[B_];
  int b = threadIdx.x;  // 32 threads, one image each
  bool anyv = false;
  for (int m = 0; m < M_; m++)
    anyv |= (targets[((size_t)b * M_ + m) * 5 + 4] != -1.0f);

  float o[12];
  const float* g = g_part + (size_t)b * BLKX * 12;
#pragma unroll
  for (int k = 0; k < 12; k++) o[k] = g[k];
  for (int c = 1; c < BLKX; c++) {
    const float* a = g + c * 12;
#pragma unroll
    for (int k = 0; k < 6; k++) o[k] += a[k];
    if (a[6] > o[6]) {
#pragma unroll
      for (int k = 6; k < 12; k++) o[k] = a[k];
    } else if (a[6] == o[6]) {
#pragma unroll
      for (int k = 7; k < 12; k++) o[k] += a[k];
    }
  }

  float loss;
  if (!anyv) {
    loss = o[5] / (float)N_;  // empty: mean bce(conf, 0)
  } else {
    float n_m = o[0], s_bb = o[1], s_nll = o[2], s_b1 = o[3], s_b0u = o[4];
    if (n_m == 0.0f) {  // fallback: matched = (best_iou == global max)
      n_m = o[7]; s_bb = o[8]; s_nll = o[9]; s_b1 = o[10];
      s_b0u = o[5] - o[11];
    }
    float ns = fmaxf(n_m, 1.0f);
    float bbox = s_bb / (ns * 4.0f);
    float cls = s_nll / ns;
    float m_conf = s_b1 / ns;
    float n_u = (float)N_ - n_m;
    float u_conf = s_b0u / fmaxf(n_u, 1.0f);
    float conf_loss = (n_u > 0.0f) ? (m_conf + u_conf) * 0.5f : m_conf;
    loss = bbox * 5.0f + cls + conf_loss * 2.0f;
  }
  sh[b] = loss;
  __syncthreads();
  if (b == 0) {
    float s = 0.0f;
    for (int i = 0; i < B_; i++) s += sh[i];
    *out = s / (float)B_;
  }
}

extern "C" void kernel_launch(void* const* d_in, const int* in_sizes, int n_in,
                              void* d_out, int out_size) {
  const float* preds = (const float*)d_in[0];
  const float* targets = (const float*)d_in[1];
  float* out = (float*)d_out;
  dim3 grid(BLKX, B_);
  det_loss_main<<<grid, 256>>>(preds, targets);
  det_loss_final<<<1, B_>>>(targets, out);
}

// round 3
// speedup vs baseline: 3.8700x; 3.8700x over previous
#include <cuda_runtime.h>
#include <math.h>

#define FULLMASK 0xffffffffu
constexpr int B_ = 32, N_ = 16384, M_ = 128, PW = 86, NLOG = 80;
constexpr int TPB = 512, BLKX = N_ / TPB;  // 32 blocks per image
constexpr int NWARP = TPB / 32;            // 16
constexpr float NEGV = -1000000000.0f;

// per-(image,chunk) partials:
// [0]=n_m [1]=s_bbox [2]=s_nll [3]=s_bce1 [4]=s_bce0_unmatched [5]=s_bce0_all
// [6]=fb_max [7]=fb_n [8]=fb_bbox [9]=fb_nll [10]=fb_bce1 [11]=fb_bce0
__device__ float g_part[B_ * BLKX * 12];

__device__ __forceinline__ float sl1(float x, float y) {
  float d = x - y, ad = fabsf(d);
  return ad < 1.0f ? 0.5f * d * d : ad - 0.5f;
}
__device__ __forceinline__ int f2ord(float f) {
  int i = __float_as_int(f);
  return i ^ ((i >> 31) & 0x7fffffff);
}
__device__ __forceinline__ float ord2f(int k) {
  return __int_as_float(k ^ ((k >> 31) & 0x7fffffff));
}

__global__ __launch_bounds__(TPB) void det_loss_main(
    const float* __restrict__ preds, const float* __restrict__ targets) {
  const int b = blockIdx.y;
  const int tid = threadIdx.x, wid = tid >> 5, lane = tid & 31;

  __shared__ float tx1[M_], ty1[M_], tx2[M_], ty2[M_], tcl[M_];
  __shared__ float4 ct[M_];
  __shared__ float cs2[M_];
  __shared__ int cixs[M_];
  __shared__ int sV;
  __shared__ float wacc[NWARP][12];

  if (tid < M_) {
    const float* t = targets + ((size_t)b * M_ + tid) * 5;
    tx1[tid] = t[0]; ty1[tid] = t[1]; tx2[tid] = t[2]; ty2[tid] = t[3]; tcl[tid] = t[4];
  }
  __syncthreads();

  // warp 0: order-preserving ballot compaction of valid targets
  if (wid == 0) {
    int base = 0;
#pragma unroll
    for (int g = 0; g < 4; g++) {
      int m = g * 32 + lane;
      bool val = tcl[m] != -1.0f;
      unsigned bal = __ballot_sync(FULLMASK, val);
      int pos = base + __popc(bal & ((1u << lane) - 1u));
      if (val) {
        ct[pos] = make_float4(tx1[m], ty1[m], tx2[m], ty2[m]);
        cs2[pos] = (tx2[m] - tx1[m]) * (ty2[m] - ty1[m]);
        cixs[pos] = m;
      }
      base += __popc(bal);
    }
    if (lane == 0) sV = base;
  }
  __syncthreads();
  const int V = sV;
  const int nc = (V + 31) >> 5;
  const int cix0 = (V > 0) ? cixs[0] : 0;

  // per-lane candidate registers: compacted targets lane, lane+32, ...
  float4 kb[4]; float ks[4]; int kix[4]; bool kok[4];
#pragma unroll
  for (int c = 0; c < 4; c++) {
    int m = lane + 32 * c;
    bool ok = m < V;
    int mm = ok ? m : 0;
    kb[c] = ct[mm]; ks[c] = cs2[mm]; kix[c] = cixs[mm]; kok[c] = ok;
  }

  // ---- one pred per thread ----
  const int n = blockIdx.x * TPB + tid;
  const float* row = preds + ((size_t)b * N_ + n) * PW;
  float2 v01 = __ldg((const float2*)row);
  float2 v23 = __ldg(((const float2*)row) + 1);
  float conf = __ldg(row + 4);
  float pb0 = v01.x, pb1 = v01.y, pb2 = v23.x, pb3 = v23.y;
  float bce0 = -fmaxf(__logf(1.0f - conf), -100.0f);
  float pdx = pb2 - pb0, pdy = pb3 - pb1;
  float a1 = pdx * pdy;

  float biou = (V > 0) ? 0.0f : NEGV;
  int bidx = cix0;

  // warp-cooperative IoU/argmax for non-degenerate preds only
  unsigned nd = __ballot_sync(FULLMASK, (pdx > 0.0f) && (pdy > 0.0f) && (V > 0));
  while (nd) {
    int L = __ffs(nd) - 1; nd &= nd - 1;
    float q0 = __shfl_sync(FULLMASK, pb0, L);
    float q1 = __shfl_sync(FULLMASK, pb1, L);
    float q2 = __shfl_sync(FULLMASK, pb2, L);
    float q3 = __shfl_sync(FULLMASK, pb3, L);
    float qa = __shfl_sync(FULLMASK, a1, L);
    float lb = NEGV; int li = cix0;
#pragma unroll
    for (int c = 0; c < 4; c++) {
      if (c >= nc) break;
      float x1 = fmaxf(q0, kb[c].x);
      float y1 = fmaxf(q1, kb[c].y);
      float x2 = fminf(q2, kb[c].z);
      float y2 = fminf(q3, kb[c].w);
      float inter = fmaxf(x2 - x1, 0.0f) * fmaxf(y2 - y1, 0.0f);
      float den = (qa + ks[c]) - inter + 1e-6f;
      float iou = __fdividef(inter, den);
      if (kok[c] && iou > lb) { lb = iou; li = kix[c]; }
    }
    int km = __reduce_max_sync(FULLMASK, f2ord(lb));
    float wv = ord2f(km);
    unsigned cand = (lb == wv) ? (unsigned)li : 0xffffffffu;
    unsigned wi = __reduce_min_sync(FULLMASK, cand);
    if (lane == L) {
      biou = (wv == 0.0f) ? 0.0f : wv;  // canonicalize -0
      bidx = (int)wi;
    }
  }

  bool matched = biou > 0.4f;
  float s_all = bce0;
  float s_b0u = matched ? 0.0f : bce0;

  // warp max of biou -> fallback candidates
  float fmx = ord2f(__reduce_max_sync(FULLMASK, f2ord(biou)));
  float n_m = 0.f, s_bb = 0.f, s_nll = 0.f, s_b1 = 0.f;
  float fn = 0.f, fbb = 0.f, fnll = 0.f, fb1 = 0.f, fb0 = 0.f;

  unsigned need = __ballot_sync(FULLMASK, matched || (biou == fmx));
  while (need) {
    int L = __ffs(need) - 1; need &= need - 1;
    float q0 = __shfl_sync(FULLMASK, pb0, L);
    float q1 = __shfl_sync(FULLMASK, pb1, L);
    float q2 = __shfl_sync(FULLMASK, pb2, L);
    float q3 = __shfl_sync(FULLMASK, pb3, L);
    float qc = __shfl_sync(FULLMASK, conf, L);
    float qb0 = __shfl_sync(FULLMASK, bce0, L);
    float qi = __shfl_sync(FULLMASK, biou, L);
    int qx = __shfl_sync(FULLMASK, bidx, L);
    const float* hrow = preds + ((size_t)b * N_ + (blockIdx.x * TPB + wid * 32 + L)) * PW;
    float l0 = __ldg(hrow + 6 + lane);
    float l1 = __ldg(hrow + 38 + lane);
    float l2 = (lane < 16) ? __ldg(hrow + 70 + lane) : -1e30f;
    float mx = fmaxf(l0, fmaxf(l1, l2));
    mx = ord2f(__reduce_max_sync(FULLMASK, f2ord(mx)));
    float se = __expf(l0 - mx) + __expf(l1 - mx) + __expf(l2 - mx);
#pragma unroll
    for (int off = 16; off; off >>= 1) se += __shfl_xor_sync(FULLMASK, se, off);
    int e = min(max((int)tcl[qx], 0), NLOG - 1);
    float lv;
    if (e < 32)      lv = __shfl_sync(FULLMASK, l0, e);
    else if (e < 64) lv = __shfl_sync(FULLMASK, l1, e - 32);
    else             lv = __shfl_sync(FULLMASK, l2, e - 64);
    float nll = (mx + __logf(se)) - lv;
    float g0 = tx1[qx], g1 = ty1[qx], g2 = tx2[qx], g3 = ty2[qx];
    float ga = (g2 - g0) * (g3 - g1);
    float w = (ga < 0.01f) ? 1.5f : 1.0f;
    float bbt = (sl1(q0, g0) + sl1(q1, g1) + sl1(q2, g2) + sl1(q3, g3)) * w;
    float bce1 = -fmaxf(__logf(qc), -100.0f);
    if (qi > 0.4f) { n_m += 1.f; s_bb += bbt; s_nll += nll; s_b1 += bce1; }
    if (qi == fmx) { fn += 1.f; fbb += bbt; fnll += nll; fb1 += bce1; fb0 += qb0; }
  }

  // reduce per-lane sums across warp
#pragma unroll
  for (int off = 16; off; off >>= 1) {
    s_all += __shfl_xor_sync(FULLMASK, s_all, off);
    s_b0u += __shfl_xor_sync(FULLMASK, s_b0u, off);
  }

  if (lane == 0) {
    float* a = wacc[wid];
    a[0] = n_m; a[1] = s_bb; a[2] = s_nll; a[3] = s_b1; a[4] = s_b0u; a[5] = s_all;
    a[6] = fmx; a[7] = fn; a[8] = fbb; a[9] = fnll; a[10] = fb1; a[11] = fb0;
  }
  __syncthreads();
  if (tid == 0) {
    float o[12];
#pragma unroll
    for (int k = 0; k < 12; k++) o[k] = wacc[0][k];
    for (int wv = 1; wv < NWARP; wv++) {
      float* a = wacc[wv];
#pragma unroll
      for (int k = 0; k < 6; k++) o[k] += a[k];
      if (a[6] > o[6]) {
#pragma unroll
        for (int k = 6; k < 12; k++) o[k] = a[k];
      } else if (a[6] == o[6]) {
#pragma unroll
        for (int k = 7; k < 12; k++) o[k] += a[k];
      }
    }
    float* g = g_part + ((size_t)b * BLKX + blockIdx.x) * 12;
#pragma unroll
    for (int k = 0; k < 12; k++) g[k] = o[k];
  }
}

__global__ __launch_bounds__(1024) void det_loss_final(
    const float* __restrict__ targets, float* __restrict__ out) {
  __shared__ float sh[B_];
  const int tid = threadIdx.x, b = tid >> 5, lane = tid & 31;

  // any-valid: 32 lanes x 4 targets
  bool av = false;
#pragma unroll
  for (int k = 0; k < 4; k++)
    av |= (targets[((size_t)b * M_ + lane * 4 + k) * 5 + 4] != -1.0f);
  bool anyv = __ballot_sync(FULLMASK, av) != 0;

  // lane = chunk; xor-shuffle tree merge (commutative: max-merge w/ tie-add)
  float o[12];
  const float* g = g_part + ((size_t)b * BLKX + lane) * 12;
#pragma unroll
  for (int k = 0; k < 12; k++) o[k] = g[k];
#pragma unroll
  for (int off = 16; off; off >>= 1) {
    float t[12];
#pragma unroll
    for (int k = 0; k < 12; k++) t[k] = __shfl_xor_sync(FULLMASK, o[k], off);
#pragma unroll
    for (int k = 0; k < 6; k++) o[k] += t[k];
    if (t[6] > o[6]) {
#pragma unroll
      for (int k = 6; k < 12; k++) o[k] = t[k];
    } else if (t[6] == o[6]) {
#pragma unroll
      for (int k = 7; k < 12; k++) o[k] += t[k];
    }
  }

  if (lane == 0) {
    float loss;
    if (!anyv) {
      loss = o[5] / (float)N_;
    } else {
      float n_m = o[0], s_bb = o[1], s_nll = o[2], s_b1 = o[3], s_b0u = o[4];
      if (n_m == 0.0f) {  // fallback: matched = (best_iou == global max)
        n_m = o[7]; s_bb = o[8]; s_nll = o[9]; s_b1 = o[10];
        s_b0u = o[5] - o[11];
      }
      float ns = fmaxf(n_m, 1.0f);
      float bbox = s_bb / (ns * 4.0f);
      float cls = s_nll / ns;
      float m_conf = s_b1 / ns;
      float n_u = (float)N_ - n_m;
      float u_conf = s_b0u / fmaxf(n_u, 1.0f);
      float conf_loss = (n_u > 0.0f) ? (m_conf + u_conf) * 0.5f : m_conf;
      loss = bbox * 5.0f + cls + conf_loss * 2.0f;
    }
    sh[b] = loss;
  }
  __syncthreads();
  if (tid < 32) {
    float v = sh[tid];
#pragma unroll
    for (int off = 16; off; off >>= 1) v += __shfl_xor_sync(FULLMASK, v, off);
    if (tid == 0) *out = v / (float)B_;
  }
}

extern "C" void kernel_launch(void* const* d_in, const int* in_sizes, int n_in,
                              void* d_out, int out_size) {
  const float* preds = (const float*)d_in[0];
  const float* targets = (const float*)d_in[1];
  float* out = (float*)d_out;
  dim3 grid(BLKX, B_);
  det_loss_main<<<grid, TPB>>>(preds, targets);
  det_loss_final<<<1, 1024>>>(targets, out);
}